// round 10
// baseline (speedup 1.0000x reference)
#include <cuda_runtime.h>

#define NB 128
#define NT 96
#define ND 256
#define NH 256
#define NCM 512
#define KA 512
#define KC 1280
#define GRID 128
#define NTHR 512
#define NGRP 8

typedef unsigned long long u64;

// smem layout (floats): b-major activation tiles
#define C_BSTR  1288
#define A_BSTR  520
#define A_ACT   (16 * C_BSTR)            // 20608
#define A_PART  (A_ACT + 8 * A_BSTR)     // 24768 (512 slots * 5-pad)
#define A_SCORE (A_PART + 2560)          // 27328
#define SMEM_FLOATS (A_SCORE + 512)      // 27840
#define SMEM_BYTES  (SMEM_FLOATS * 4)    // 111360 B

// ---------------- static device scratch ----------------
__device__ float g_Zb [NB*NT*ND];        // [b][t][d]
__device__ float g_ZPb[NB*NT*ND];
__device__ float g_LPb[NB*NT*ND];
__device__ float g_hall[(NT+1)*NB*NH];   // [t][b][h]
__device__ float g_sw  [NB*NCM];         // [b][cm]
__device__ float g_mm  [NCM*ND];
__device__ float g_memT[ND*NCM];
__device__ float g_W4r [4*NH*KC];        // row-major folded gate weights (dc0 part)
__device__ float g_W4p [4*NH*768];       // dc1 partial for cols [512:1280)
__device__ float g_W4q [4*NH*KC + 4096]; // blocked [g][k4][hh][4k], padded for prefetch
__device__ float g_b4a [4*NH];
__device__ float g_b4b [4*NH];
__device__ float g_b4  [4*NH];
__device__ float g_Wscr[NCM*KA];
__device__ float g_Wscq[NCM*KA + 6144];  // blocked [k4][cm][4k], padded for prefetch
__device__ float g_csc [NCM];
__device__ unsigned int g_garrive [NGRP*64];
__device__ unsigned int g_grelease[NGRP*64];

#define FMA4(ACC, WV, AV) ACC = fmaf((WV).x,(AV).x, fmaf((WV).y,(AV).y, fmaf((WV).z,(AV).z, fmaf((WV).w,(AV).w,(ACC)))))

// ---- packed fp32x2: lanes = (even-k, odd-k) partials; no dup needed ----
__device__ __forceinline__ void ffma2(u64& acc, u64 a, u64 b) {
    asm("fma.rn.f32x2 %0, %1, %2, %0;" : "+l"(acc) : "l"(a), "l"(b));
}
__device__ __forceinline__ void unpack2(u64 v, float& lo, float& hi) {
    asm("mov.b64 {%0, %1}, %2;" : "=f"(lo), "=f"(hi) : "l"(v));
}
__device__ __forceinline__ float pairsum(u64 v) {
    float lo, hi; unpack2(v, lo, hi); return lo + hi;
}

// ---- acquire/release sync primitives ----
__device__ __forceinline__ unsigned atom_add_acqrel(unsigned* p, unsigned v) {
    unsigned r;
    asm volatile("atom.acq_rel.gpu.add.u32 %0, [%1], %2;" : "=r"(r) : "l"(p), "r"(v) : "memory");
    return r;
}
__device__ __forceinline__ unsigned ld_acquire(unsigned* p) {
    unsigned r;
    asm volatile("ld.acquire.gpu.u32 %0, [%1];" : "=r"(r) : "l"(p) : "memory");
    return r;
}
__device__ __forceinline__ void st_release(unsigned* p, unsigned v) {
    asm volatile("st.release.gpu.u32 [%0], %1;" :: "l"(p), "r"(v) : "memory");
}

// ---------------- prep1 ----------------
__global__ void prep1(const float* __restrict__ x, const float* __restrict__ xmean,
                      const int* __restrict__ cl32,
                      const float* __restrict__ gz_w,  const float* __restrict__ gz_b,
                      const float* __restrict__ gzp_w, const float* __restrict__ gzp_b,
                      const float* __restrict__ memory, const float* __restrict__ local_w)
{
    int tid  = blockIdx.x * blockDim.x + threadIdx.x;
    int nthr = gridDim.x * blockDim.x;
    bool is64 = (cl32[1] == 0);   // cluster vals 1..8 -> int64 high word of elem0 is 0

    for (int i = tid; i < NB*NT*ND; i += nthr) {
        int d = i & (ND - 1);
        int t = (i / ND) % NT;
        int b = i / (ND * NT);
        long long o = (((long long)b * 6) * NT + t) * ND + d;
        float xt  = x[o];
        float xl  = x[o + 1ll*NT*ND];
        float mk  = x[o + 2ll*NT*ND];
        float dt  = x[o + 3ll*NT*ND];
        float xlb = x[o + 4ll*NT*ND];
        float dtb = x[o + 5ll*NT*ND];
        float mean = xmean[t*ND + d];
        float dz  = expf(-fmaxf(dt  * gz_w[d]  + gz_b[d],  0.f));
        float dzp = expf(-fmaxf(dtb * gzp_w[d] + gzp_b[d], 0.f));
        float z  = mk*xt + (1.f - mk)*(dz *xl  + (1.f - dz )*mean);
        float zp = mk*xt + (1.f - mk)*(dzp*xlb + (1.f - dzp)*mean);
        g_Zb[i]  = z;
        g_ZPb[i] = zp;
        g_LPb[i] = local_w[d]*z + local_w[ND + d]*zp;
    }
    for (int i = tid; i < NCM*ND; i += nthr) {
        int d  = i & (ND - 1);
        int c  = i / (64 * ND);
        int cv = is64 ? cl32[2*d] : cl32[d];
        g_mm[i] = (cv == c + 1) ? memory[i] : 0.f;
    }
    for (int i = tid; i < ND*NCM; i += nthr) {
        int d = i / NCM, cm = i % NCM;
        g_memT[i] = memory[cm*ND + d];
    }
    for (int i = tid; i < NB*NH; i += nthr) g_hall[i] = 0.f;
    if (tid < NGRP*64) { g_garrive[tid] = 0u; g_grelease[tid] = 0u; }
}

// ---------------- prep2: folded score weights + csc ----------------
__global__ void prep2(const float* __restrict__ W_fc, const float* __restrict__ b_fc,
                      const float* __restrict__ local_w)
{
    __shared__ float A[16*256];
    int cmt = blockIdx.x;            // 0..31
    int tid = threadIdx.x;           // 512
    for (int idx = tid; idx < 16*256; idx += 512) {
        int ci = idx >> 8, d = idx & 255;
        float mmv = g_mm[(cmt*16 + ci)*ND + d];
        A[idx] = local_w[2*ND + d] * mmv;
        g_Wscr[(cmt*16 + ci)*KA + d] = mmv;
    }
    __syncthreads();
    int j = tid & 255, half = tid >> 8;
    float acc[8];
    #pragma unroll
    for (int i = 0; i < 8; ++i) acc[i] = 0.f;
    for (int d = 0; d < 256; ++d) {
        float wf = W_fc[d*ND + j];
        #pragma unroll
        for (int i = 0; i < 8; ++i) acc[i] = fmaf(A[(half*8+i)*256 + d], wf, acc[i]);
    }
    #pragma unroll
    for (int i = 0; i < 8; ++i)
        g_Wscr[(cmt*16 + half*8 + i)*KA + 256 + j] = acc[i];
    if (tid < 16) {
        float s = 0.f;
        for (int d = 0; d < 256; ++d) s += A[tid*256 + d] * b_fc[d];
        g_csc[cmt*16 + tid] = s;
    }
}

// ---------------- prep3: folded gate weights, 2-way d-split ----------------
__global__ void prep3(const float* __restrict__ W_i, const float* __restrict__ W_f,
                      const float* __restrict__ W_o, const float* __restrict__ W_c,
                      const float* __restrict__ b_i, const float* __restrict__ b_f,
                      const float* __restrict__ b_o, const float* __restrict__ b_c,
                      const float* __restrict__ W_fc, const float* __restrict__ b_fc)
{
    __shared__ float A1[16*128];
    __shared__ float A2[16*128];
    int bx = blockIdx.x;                 // 128 blocks
    int g = bx >> 5, hht = (bx >> 1) & 15, dc = bx & 1;
    int d0 = dc * 128;
    const float* Wg = (g == 0) ? W_i : (g == 1) ? W_f : (g == 2) ? W_o : W_c;
    const float* bg = (g == 0) ? b_i : (g == 1) ? b_f : (g == 2) ? b_o : b_c;
    int tid = threadIdx.x;   // 512

    for (int idx = tid; idx < 16*128; idx += 512) {
        int hi = idx >> 7, d = idx & 127;
        int row = hht*16 + hi;
        A1[idx] = Wg[row*KC + 768 + d0 + d];
        A2[idx] = Wg[row*KC + 512 + d0 + d];
    }
    if (dc == 0) {
        for (int idx = tid; idx < 16*512; idx += 512) {   // z,zp verbatim
            int hi = idx >> 9, k = idx & 511;
            int row = hht*16 + hi;
            g_W4r[(g*NH + row)*KC + k] = Wg[row*KC + k];
        }
    }
    __syncthreads();
    {   // h segment partial over this d half
        int j = tid & 255, half = tid >> 8;
        float acc[8];
        #pragma unroll
        for (int i = 0; i < 8; ++i) acc[i] = 0.f;
        for (int d = 0; d < 128; ++d) {
            float wf = W_fc[(d0 + d)*ND + j];
            #pragma unroll
            for (int i = 0; i < 8; ++i) acc[i] = fmaf(A2[(half*8+i)*128 + d], wf, acc[i]);
        }
        #pragma unroll
        for (int i = 0; i < 8; ++i) {
            int hhr = hht*16 + half*8 + i;
            if (dc == 0) g_W4r[(g*NH + hhr)*KC + 1024 + j] = Wg[hhr*KC + 1024 + j] + acc[i];
            else         g_W4p[(g*NH + hhr)*768 + 512 + j] = acc[i];
        }
    }
    {   // s' segment partial
        int cm = tid;
        float acc[16];
        #pragma unroll
        for (int i = 0; i < 16; ++i) acc[i] = 0.f;
        for (int d = 0; d < 128; ++d) {
            float mt = g_memT[(d0 + d)*NCM + cm];
            #pragma unroll
            for (int i = 0; i < 16; ++i) acc[i] = fmaf(A1[i*128 + d], mt, acc[i]);
        }
        #pragma unroll
        for (int i = 0; i < 16; ++i) {
            if (dc == 0) g_W4r[(g*NH + hht*16 + i)*KC + 512 + cm] = acc[i];
            else         g_W4p[(g*NH + hht*16 + i)*768 + cm] = acc[i];
        }
    }
    if (tid < 16) {   // bias partial
        float s = 0.f;
        for (int d = 0; d < 128; ++d) s += A2[tid*128 + d] * b_fc[d0 + d];
        if (dc == 0) g_b4a[g*NH + hht*16 + tid] = bg[hht*16 + tid] + s;
        else         g_b4b[g*NH + hht*16 + tid] = s;
    }
}

// ---------------- prep4: combine partials, blocked layouts, bias ----------------
__global__ void prep4()
{
    int idx = blockIdx.x * blockDim.x + threadIdx.x;
    if (idx < 4*320*256) {
        int hh = idx & 255;
        int gk = idx >> 8;
        int g = gk / 320, k4 = gk % 320;
        float4 v = *(const float4*)&g_W4r[(g*NH + hh)*KC + k4*4];
        if (k4 >= 128) {
            float4 p = *(const float4*)&g_W4p[(g*NH + hh)*768 + (k4 - 128)*4];
            v.x += p.x; v.y += p.y; v.z += p.z; v.w += p.w;
        }
        *(float4*)&g_W4q[idx*4] = v;
        return;
    }
    int j = idx - 4*320*256;
    if (j < 128*512) {
        int cm = j & 511, k4 = j >> 9;
        *(float4*)&g_Wscq[j*4] = *(const float4*)&g_Wscr[cm*KA + k4*4];
        return;
    }
    int m = j - 128*512;
    if (m < 4*NH) g_b4[m] = g_b4a[m] + g_b4b[m];
}

// ---------------- tiny barrier-reset (keeps launch count; idempotent) ----------------
__global__ void prep5()
{
    int tid = threadIdx.x;
    if (tid < NGRP*64) { g_garrive[tid] = 0u; g_grelease[tid] = 0u; }
}

// ---------------- per-group barrier ----------------
__device__ __forceinline__ void group_sync(int grp, unsigned int& gen)
{
    __syncthreads();
    if (threadIdx.x == 0) {
        unsigned int target = gen + 1u;
        unsigned int a = atom_add_acqrel(&g_garrive[grp*64], 1u) + 1u;
        if (a == target * 16u) {
            st_release(&g_grelease[grp*64], target);
        } else {
            while (ld_acquire(&g_grelease[grp*64]) < target) { }
        }
    }
    gen += 1u;
    __syncthreads();
}

// ---------------- persistent recurrence (k-pair packed f32x2, b-major acts) ----------------
__global__ void __launch_bounds__(NTHR, 1)
rnn_kernel(const float* __restrict__ global_w)
{
    extern __shared__ float sm[];
    const int cta = blockIdx.x, tid = threadIdx.x;
    const int lane = tid & 31, wid = tid >> 5;
    const int grp = cta >> 4, local = cta & 15;
    const int bhalf = local >> 3, ccl = local & 7;
    const int a_b0 = grp*16 + bhalf*8;
    const int a_ml = tid & 63, a_bh = (tid >> 6) & 1, a_ks = tid >> 7;
    const int sub = local;
    const int c_b0 = grp*16;
    const int c_hl = tid & 15, c_ks = tid >> 6;
    const int hh = sub*16 + c_hl;
    unsigned int gen = 0;

    // ---- register hoists ----
    float gwreg = global_w[ccl];
    float cscreg = g_csc[ccl*64 + (tid & 63)];
    float creg = 0.f;
    float bias0 = 0.f, bias1 = 0.f, bias2 = 0.f, bias3 = 0.f;
    if (tid < 256) {
        int h2 = sub*16 + (tid & 15);
        bias0 = g_b4[0*NH + h2];
        bias1 = g_b4[1*NH + h2];
        bias2 = g_b4[2*NH + h2];
        bias3 = g_b4[3*NH + h2];
    }

    // pre-stage A acts for t=0: [bi 0..7][k 0..511] (LP then h)
    for (int idx = tid; idx < 8*128; idx += NTHR) {
        int bi = idx >> 7, k4 = idx & 127;
        int b = a_b0 + bi;
        float4 v;
        if (k4 < 64) v = *(const float4*)&g_LPb[((b*NT) << 8) + k4*4];
        else         v = __ldcg((const float4*)&g_hall[(b << 8) + (k4-64)*4]);
        *(float4*)&sm[A_ACT + bi*A_BSTR + k4*4] = v;
    }
    __syncthreads();

    for (int t = 0; t < NT; ++t) {
        // ===== Phase A: scores + softmax -> s'(t) in g_sw [b][cm] =====
        {
            u64 acc2[4] = {0ull, 0ull, 0ull, 0ull};
            {
                const double2* wp = (const double2*)g_Wscq + (a_ks*32)*NCM + (ccl*64 + a_ml);
                const float*  ak = sm + A_ACT + (a_bh*4)*A_BSTR + a_ks*128;
                #define AHALF(IT, WV) { \
                    u64 w01_ = __double_as_longlong((WV).x); \
                    u64 w23_ = __double_as_longlong((WV).y); \
                    const float* app_ = ak + (IT)*4; \
                    _Pragma("unroll") \
                    for (int j_ = 0; j_ < 4; ++j_) { \
                        u64 a01_ = *(const u64*)(app_ + j_*A_BSTR); \
                        u64 a23_ = *(const u64*)(app_ + j_*A_BSTR + 2); \
                        ffma2(acc2[j_], w01_, a01_); \
                        ffma2(acc2[j_], w23_, a23_); } }
                double2 V0 = wp[0], V1 = wp[NCM];
                #pragma unroll 1
                for (int it = 0; it < 32; it += 2) {
                    double2 N0 = wp[(it+2)*NCM];     // prefetch (padded array)
                    AHALF(it, V0)
                    double2 N1 = wp[(it+3)*NCM];
                    AHALF(it+1, V1)
                    V0 = N0; V1 = N1;
                }
                #undef AHALF
            }
            {
                int base = A_PART + ((a_ks*64 + a_ml)*2 + a_bh)*5;
                #pragma unroll
                for (int j = 0; j < 4; ++j) sm[base + j] = pairsum(acc2[j]);
            }
            __syncthreads();
            {   // reduce over a_ks + csc bias; bl = batch (bh=bl>>2, j=bl&3)
                int bl = tid >> 6, m = tid & 63;
                float s = cscreg;
                #pragma unroll
                for (int ks = 0; ks < 4; ++ks)
                    s += sm[A_PART + ((ks*64 + m)*2 + (bl >> 2))*5 + (bl & 3)];
                sm[A_SCORE + bl*64 + m] = s;
            }
            __syncthreads();
            if (wid < 8) {   // softmax for batch wid; scale by global_w[ccl]
                float v0 = sm[A_SCORE + wid*64 + lane];
                float v1 = sm[A_SCORE + wid*64 + 32 + lane];
                float mx = fmaxf(v0, v1);
                #pragma unroll
                for (int o = 16; o; o >>= 1) mx = fmaxf(mx, __shfl_xor_sync(0xffffffffu, mx, o));
                float e0 = expf(v0 - mx), e1 = expf(v1 - mx);
                float s = e0 + e1;
                #pragma unroll
                for (int o = 16; o; o >>= 1) s += __shfl_xor_sync(0xffffffffu, s, o);
                float sc = gwreg / s;
                int b = a_b0 + wid;
                __stcg(&g_sw[b*NCM + ccl*64 + lane],      e0*sc);
                __stcg(&g_sw[b*NCM + ccl*64 + 32 + lane], e1*sc);
            }
        }

        // stage C z/zp(t) (h-independent) BEFORE the barrier: [bi][k<512]
        for (int idx = tid; idx < 16*128; idx += NTHR) {
            int bi = idx >> 7, k4 = idx & 127;
            int b = c_b0 + bi, k = k4*4;
            float4 v;
            if (k < 256) v = *(const float4*)&g_Zb [((b*NT + t) << 8) + k];
            else         v = *(const float4*)&g_ZPb[((b*NT + t) << 8) + (k - 256)];
            *(float4*)&sm[bi*C_BSTR + k] = v;
        }
        group_sync(grp, gen);

        // stage C s'(t) + h(t): [bi][k 512..1280)
        for (int idx = tid; idx < 16*192; idx += NTHR) {
            int bi = idx / 192, kr4 = idx % 192;
            int b = c_b0 + bi, k = 512 + kr4*4;
            float4 v;
            if (k < 1024) v = __ldcg((const float4*)&g_sw[(b << 9) + (k - 512)]);
            else          v = __ldcg((const float4*)&g_hall[((t*NB + b) << 8) + (k - 1024)]);
            *(float4*)&sm[bi*C_BSTR + k] = v;
        }
        __syncthreads();

        // ===== Phase C: 4-gate GEMM, K=1280, k-pair packed f32x2 =====
        {
            u64 acc2[16];
            #pragma unroll
            for (int i = 0; i < 16; ++i) acc2[i] = 0ull;
            {
                const int c_bq = (tid >> 4) & 3;
                const int k40 = c_ks * 40;
                const double2* w0 = (const double2*)g_W4q + ((0*320 + k40)*NH + hh);
                const double2* w1 = (const double2*)g_W4q + ((1*320 + k40)*NH + hh);
                const double2* w2 = (const double2*)g_W4q + ((2*320 + k40)*NH + hh);
                const double2* w3 = (const double2*)g_W4q + ((3*320 + k40)*NH + hh);
                const float*  ak = sm + (c_bq*4)*C_BSTR + c_ks*160;
                #define CHALF(IT, WA, WB, WC, WD) { \
                    u64 wa01_ = __double_as_longlong((WA).x), wa23_ = __double_as_longlong((WA).y); \
                    u64 wb01_ = __double_as_longlong((WB).x), wb23_ = __double_as_longlong((WB).y); \
                    u64 wc01_ = __double_as_longlong((WC).x), wc23_ = __double_as_longlong((WC).y); \
                    u64 wd01_ = __double_as_longlong((WD).x), wd23_ = __double_as_longlong((WD).y); \
                    const float* app_ = ak + (IT)*4; \
                    _Pragma("unroll") \
                    for (int j_ = 0; j_ < 4; ++j_) { \
                        u64 a01_ = *(const u64*)(app_ + j_*C_BSTR); \
                        u64 a23_ = *(const u64*)(app_ + j_*C_BSTR + 2); \
                        ffma2(acc2[0*4+j_], wa01_, a01_); ffma2(acc2[0*4+j_], wa23_, a23_); \
                        ffma2(acc2[1*4+j_], wb01_, a01_); ffma2(acc2[1*4+j_], wb23_, a23_); \
                        ffma2(acc2[2*4+j_], wc01_, a01_); ffma2(acc2[2*4+j_], wc23_, a23_); \
                        ffma2(acc2[3*4+j_], wd01_, a01_); ffma2(acc2[3*4+j_], wd23_, a23_); } }
                double2 Wa0 = w0[0],  Wb0 = w1[0],  Wc0 = w2[0],  Wd0 = w3[0];
                double2 Wa1 = w0[NH], Wb1 = w1[NH], Wc1 = w2[NH], Wd1 = w3[NH];
                #pragma unroll 1
                for (int it = 0; it < 40; it += 2) {
                    double2 Na = w0[(it+2)*NH], Nb = w1[(it+2)*NH],
                            Nc = w2[(it+2)*NH], Nd = w3[(it+2)*NH];   // prefetch (padded)
                    CHALF(it, Wa0, Wb0, Wc0, Wd0)
                    double2 Ma = w0[(it+3)*NH], Mb = w1[(it+3)*NH],
                            Mc = w2[(it+3)*NH], Md = w3[(it+3)*NH];
                    CHALF(it+1, Wa1, Wb1, Wc1, Wd1)
                    Wa0 = Na; Wb0 = Nb; Wc0 = Nc; Wd0 = Nd;
                    Wa1 = Ma; Wb1 = Mb; Wc1 = Mc; Wd1 = Md;
                }
                #undef CHALF
            }
            __syncthreads();
            {
                const int c_bq = (tid >> 4) & 3;
                int base = (c_ks*64 + c_bq*16 + c_hl)*17;   // pad-17: conflict-free
                #pragma unroll
                for (int v = 0; v < 16; ++v) sm[base + v] = pairsum(acc2[v]);
            }
            __syncthreads();
            if (tid < 256) {   // (hl2:16, bi:16): reduce, gates, register state
                int hl2 = tid & 15, bi = tid >> 4;
                int bq = bi >> 2, j = bi & 3;
                int b = c_b0 + bi, h2 = sub*16 + hl2;
                float g0 = bias0, g1 = bias1, g2 = bias2, g3 = bias3;
                #pragma unroll
                for (int ks = 0; ks < 8; ++ks) {
                    const float* p = &sm[(ks*64 + bq*16 + hl2)*17 + j];
                    g0 += p[0]; g1 += p[4]; g2 += p[8]; g3 += p[12];
                }
                float ig = 1.f / (1.f + expf(-g0));
                float fg = 1.f / (1.f + expf(-g1));
                float og = 1.f / (1.f + expf(-g2));
                float cg = tanhf(g3);
                creg = fg * creg + ig * cg;
                float hn = og * tanhf(creg);
                __stcg(&g_hall[(((t+1)*NB + b) << 8) + h2], hn);
            }
        }

        // stage A LP(t+1) BEFORE the barrier: [bi][k<256]
        if (t + 1 < NT) {
            for (int idx = tid; idx < 8*64; idx += NTHR) {
                int bi = idx >> 6, k4 = idx & 63;
                int b = a_b0 + bi;
                *(float4*)&sm[A_ACT + bi*A_BSTR + k4*4] =
                    *(const float4*)&g_LPb[((b*NT + t + 1) << 8) + k4*4];
            }
        }
        group_sync(grp, gen);

        if (t + 1 < NT) {   // stage A h(t+1): [bi][256..512)
            for (int idx = tid; idx < 8*64; idx += NTHR) {
                int bi = idx >> 6, k4 = idx & 63;
                int b = a_b0 + bi;
                *(float4*)&sm[A_ACT + bi*A_BSTR + 256 + k4*4] =
                    __ldcg((const float4*)&g_hall[(((t+1)*NB + b) << 8) + k4*4]);
            }
            __syncthreads();
        }
    }
}

// ---------------- final: out[b,t,:] = h_{t+1} @ W_fc^T + b_fc ----------------
__global__ void out_gemm(const float* __restrict__ W_fc, const float* __restrict__ b_fc,
                         float* __restrict__ out)
{
    __shared__ float sa[16*256];
    int rt = blockIdx.x >> 2, dt = blockIdx.x & 3;
    int tid = threadIdx.x;           // 256
    int r0 = rt * 16;
    for (int idx = tid; idx < 16*64; idx += 256) {
        int row = idx >> 6, k4 = idx & 63;
        int r = r0 + row, b = r / NT, t = r % NT;
        *(float4*)&sa[row*256 + k4*4] =
            *(const float4*)&g_hall[(((t+1)*NB + b) << 8) + k4*4];
    }
    __syncthreads();
    int dl = tid & 63, rl = tid >> 6;
    int d = dt*64 + dl;
    float acc[4];
    #pragma unroll
    for (int i = 0; i < 4; ++i) acc[i] = 0.f;
    const float* wrow = W_fc + d*NH;
    #pragma unroll 4
    for (int k4 = 0; k4 < 64; ++k4) {
        float4 wv = *(const float4*)(wrow + k4*4);
        #pragma unroll
        for (int i = 0; i < 4; ++i) {
            float4 av = *(const float4*)&sa[(rl*4 + i)*256 + k4*4];
            FMA4(acc[i], wv, av);
        }
    }
    float bb = b_fc[d];
    #pragma unroll
    for (int i = 0; i < 4; ++i)
        out[(r0 + rl*4 + i)*ND + d] = acc[i] + bb;
}

// ---------------- launch ----------------
extern "C" void kernel_launch(void* const* d_in, const int* in_sizes, int n_in,
                              void* d_out, int out_size)
{
    const float* x        = (const float*)d_in[0];
    const float* xmean    = (const float*)d_in[1];
    const int*   clus     = (const int*)  d_in[2];
    const float* W_i      = (const float*)d_in[3];
    const float* b_i      = (const float*)d_in[4];
    const float* W_f      = (const float*)d_in[5];
    const float* b_f      = (const float*)d_in[6];
    const float* W_o      = (const float*)d_in[7];
    const float* b_o      = (const float*)d_in[8];
    const float* W_c      = (const float*)d_in[9];
    const float* b_c      = (const float*)d_in[10];
    const float* W_fc     = (const float*)d_in[11];
    const float* b_fc     = (const float*)d_in[12];
    const float* gz_w     = (const float*)d_in[13];
    const float* gz_b     = (const float*)d_in[14];
    const float* gzp_w    = (const float*)d_in[15];
    const float* gzp_b    = (const float*)d_in[16];
    const float* memory   = (const float*)d_in[17];
    const float* local_w  = (const float*)d_in[18];
    const float* global_w = (const float*)d_in[19];
    float* out = (float*)d_out;

    cudaFuncSetAttribute(rnn_kernel, cudaFuncAttributeMaxDynamicSharedMemorySize, SMEM_BYTES);

    prep1<<<512, 256>>>(x, xmean, clus, gz_w, gz_b, gzp_w, gzp_b, memory, local_w);
    prep2<<<32, 512>>>(W_fc, b_fc, local_w);
    prep3<<<128, 512>>>(W_i, W_f, W_o, W_c, b_i, b_f, b_o, b_c, W_fc, b_fc);
    prep4<<<1540, 256>>>();
    prep5<<<1, 512>>>();
    rnn_kernel<<<GRID, NTHR, SMEM_BYTES>>>(global_w);
    out_gemm<<<3072, 256>>>(W_fc, b_fc, out);
}

// round 11
// speedup vs baseline: 1.0015x; 1.0015x over previous
#include <cuda_runtime.h>

#define NB 128
#define NT 96
#define ND 256
#define NH 256
#define NCM 512
#define KA 512
#define KC 1280
#define GRID 128
#define NTHR 512
#define NGRP 8

typedef unsigned long long u64;

// smem layout (floats): b-major activation tiles
#define C_BSTR  1288
#define A_BSTR  520
#define A_ACT   (16 * C_BSTR)            // 20608
#define A_PART  (A_ACT + 8 * A_BSTR)     // 24768 (512 slots * 5-pad)
#define A_SCORE (A_PART + 2560)          // 27328
#define SMEM_FLOATS (A_SCORE + 512)      // 27840
#define SMEM_BYTES  (SMEM_FLOATS * 4)    // 111360 B

// ---------------- static device scratch ----------------
__device__ float g_Zb [NB*NT*ND];        // [b][t][d]
__device__ float g_ZPb[NB*NT*ND];
__device__ float g_LPb[NB*NT*ND];
__device__ float g_hall[(NT+1)*NB*NH];   // [t][b][h]
__device__ float g_sw  [NB*NCM];         // [b][cm]
__device__ float g_mm  [NCM*ND];
__device__ float g_memT[ND*NCM];
__device__ float g_W4r [4*NH*KC];        // row-major folded gate weights (dc0 part)
__device__ float g_W4p [4*NH*768];       // dc1 partial for cols [512:1280)
__device__ float g_W4q [4*NH*KC + 4096]; // blocked [g][k4][hh][4k], padded for prefetch
__device__ float g_b4a [4*NH];
__device__ float g_b4b [4*NH];
__device__ float g_b4  [4*NH];
__device__ float g_Wscr[NCM*KA];
__device__ float g_Wscq[NCM*KA + 6144];  // blocked [k4][cm][4k], padded for prefetch
__device__ float g_csc [NCM];
__device__ unsigned int g_garrive [NGRP*64];
__device__ unsigned int g_grelease[NGRP*64];

#define FMA4(ACC, WV, AV) ACC = fmaf((WV).x,(AV).x, fmaf((WV).y,(AV).y, fmaf((WV).z,(AV).z, fmaf((WV).w,(AV).w,(ACC)))))

// ---- packed fp32x2: lanes = (even-k, odd-k) partials; no dup needed ----
__device__ __forceinline__ void ffma2(u64& acc, u64 a, u64 b) {
    asm("fma.rn.f32x2 %0, %1, %2, %0;" : "+l"(acc) : "l"(a), "l"(b));
}
__device__ __forceinline__ void unpack2(u64 v, float& lo, float& hi) {
    asm("mov.b64 {%0, %1}, %2;" : "=f"(lo), "=f"(hi) : "l"(v));
}
__device__ __forceinline__ float pairsum(u64 v) {
    float lo, hi; unpack2(v, lo, hi); return lo + hi;
}

// ---- acquire/release sync primitives ----
__device__ __forceinline__ unsigned atom_add_acqrel(unsigned* p, unsigned v) {
    unsigned r;
    asm volatile("atom.acq_rel.gpu.add.u32 %0, [%1], %2;" : "=r"(r) : "l"(p), "r"(v) : "memory");
    return r;
}
__device__ __forceinline__ unsigned ld_acquire(unsigned* p) {
    unsigned r;
    asm volatile("ld.acquire.gpu.u32 %0, [%1];" : "=r"(r) : "l"(p) : "memory");
    return r;
}
__device__ __forceinline__ void st_release(unsigned* p, unsigned v) {
    asm volatile("st.release.gpu.u32 [%0], %1;" :: "l"(p), "r"(v) : "memory");
}

// ---------------- prep1 ----------------
__global__ void prep1(const float* __restrict__ x, const float* __restrict__ xmean,
                      const int* __restrict__ cl32,
                      const float* __restrict__ gz_w,  const float* __restrict__ gz_b,
                      const float* __restrict__ gzp_w, const float* __restrict__ gzp_b,
                      const float* __restrict__ memory, const float* __restrict__ local_w)
{
    int tid  = blockIdx.x * blockDim.x + threadIdx.x;
    int nthr = gridDim.x * blockDim.x;
    bool is64 = (cl32[1] == 0);   // cluster vals 1..8 -> int64 high word of elem0 is 0

    for (int i = tid; i < NB*NT*ND; i += nthr) {
        int d = i & (ND - 1);
        int t = (i / ND) % NT;
        int b = i / (ND * NT);
        long long o = (((long long)b * 6) * NT + t) * ND + d;
        float xt  = x[o];
        float xl  = x[o + 1ll*NT*ND];
        float mk  = x[o + 2ll*NT*ND];
        float dt  = x[o + 3ll*NT*ND];
        float xlb = x[o + 4ll*NT*ND];
        float dtb = x[o + 5ll*NT*ND];
        float mean = xmean[t*ND + d];
        float dz  = expf(-fmaxf(dt  * gz_w[d]  + gz_b[d],  0.f));
        float dzp = expf(-fmaxf(dtb * gzp_w[d] + gzp_b[d], 0.f));
        float z  = mk*xt + (1.f - mk)*(dz *xl  + (1.f - dz )*mean);
        float zp = mk*xt + (1.f - mk)*(dzp*xlb + (1.f - dzp)*mean);
        g_Zb[i]  = z;
        g_ZPb[i] = zp;
        g_LPb[i] = local_w[d]*z + local_w[ND + d]*zp;
    }
    for (int i = tid; i < NCM*ND; i += nthr) {
        int d  = i & (ND - 1);
        int c  = i / (64 * ND);
        int cv = is64 ? cl32[2*d] : cl32[d];
        g_mm[i] = (cv == c + 1) ? memory[i] : 0.f;
    }
    for (int i = tid; i < ND*NCM; i += nthr) {
        int d = i / NCM, cm = i % NCM;
        g_memT[i] = memory[cm*ND + d];
    }
    for (int i = tid; i < NB*NH; i += nthr) g_hall[i] = 0.f;
    if (tid < NGRP*64) { g_garrive[tid] = 0u; g_grelease[tid] = 0u; }
}

// ---------------- prep2: folded score weights + csc ----------------
__global__ void prep2(const float* __restrict__ W_fc, const float* __restrict__ b_fc,
                      const float* __restrict__ local_w)
{
    __shared__ float A[16*256];
    int cmt = blockIdx.x;            // 0..31
    int tid = threadIdx.x;           // 512
    for (int idx = tid; idx < 16*256; idx += 512) {
        int ci = idx >> 8, d = idx & 255;
        float mmv = g_mm[(cmt*16 + ci)*ND + d];
        A[idx] = local_w[2*ND + d] * mmv;
        g_Wscr[(cmt*16 + ci)*KA + d] = mmv;
    }
    __syncthreads();
    int j = tid & 255, half = tid >> 8;
    float acc[8];
    #pragma unroll
    for (int i = 0; i < 8; ++i) acc[i] = 0.f;
    for (int d = 0; d < 256; ++d) {
        float wf = W_fc[d*ND + j];
        #pragma unroll
        for (int i = 0; i < 8; ++i) acc[i] = fmaf(A[(half*8+i)*256 + d], wf, acc[i]);
    }
    #pragma unroll
    for (int i = 0; i < 8; ++i)
        g_Wscr[(cmt*16 + half*8 + i)*KA + 256 + j] = acc[i];
    if (tid < 16) {
        float s = 0.f;
        for (int d = 0; d < 256; ++d) s += A[tid*256 + d] * b_fc[d];
        g_csc[cmt*16 + tid] = s;
    }
}

// ---------------- prep3: folded gate weights, 2-way d-split ----------------
__global__ void prep3(const float* __restrict__ W_i, const float* __restrict__ W_f,
                      const float* __restrict__ W_o, const float* __restrict__ W_c,
                      const float* __restrict__ b_i, const float* __restrict__ b_f,
                      const float* __restrict__ b_o, const float* __restrict__ b_c,
                      const float* __restrict__ W_fc, const float* __restrict__ b_fc)
{
    __shared__ float A1[16*128];
    __shared__ float A2[16*128];
    int bx = blockIdx.x;                 // 128 blocks
    int g = bx >> 5, hht = (bx >> 1) & 15, dc = bx & 1;
    int d0 = dc * 128;
    const float* Wg = (g == 0) ? W_i : (g == 1) ? W_f : (g == 2) ? W_o : W_c;
    const float* bg = (g == 0) ? b_i : (g == 1) ? b_f : (g == 2) ? b_o : b_c;
    int tid = threadIdx.x;   // 512

    for (int idx = tid; idx < 16*128; idx += 512) {
        int hi = idx >> 7, d = idx & 127;
        int row = hht*16 + hi;
        A1[idx] = Wg[row*KC + 768 + d0 + d];
        A2[idx] = Wg[row*KC + 512 + d0 + d];
    }
    if (dc == 0) {
        for (int idx = tid; idx < 16*512; idx += 512) {   // z,zp verbatim
            int hi = idx >> 9, k = idx & 511;
            int row = hht*16 + hi;
            g_W4r[(g*NH + row)*KC + k] = Wg[row*KC + k];
        }
    }
    __syncthreads();
    {   // h segment partial over this d half
        int j = tid & 255, half = tid >> 8;
        float acc[8];
        #pragma unroll
        for (int i = 0; i < 8; ++i) acc[i] = 0.f;
        for (int d = 0; d < 128; ++d) {
            float wf = W_fc[(d0 + d)*ND + j];
            #pragma unroll
            for (int i = 0; i < 8; ++i) acc[i] = fmaf(A2[(half*8+i)*128 + d], wf, acc[i]);
        }
        #pragma unroll
        for (int i = 0; i < 8; ++i) {
            int hhr = hht*16 + half*8 + i;
            if (dc == 0) g_W4r[(g*NH + hhr)*KC + 1024 + j] = Wg[hhr*KC + 1024 + j] + acc[i];
            else         g_W4p[(g*NH + hhr)*768 + 512 + j] = acc[i];
        }
    }
    {   // s' segment partial
        int cm = tid;
        float acc[16];
        #pragma unroll
        for (int i = 0; i < 16; ++i) acc[i] = 0.f;
        for (int d = 0; d < 128; ++d) {
            float mt = g_memT[(d0 + d)*NCM + cm];
            #pragma unroll
            for (int i = 0; i < 16; ++i) acc[i] = fmaf(A1[i*128 + d], mt, acc[i]);
        }
        #pragma unroll
        for (int i = 0; i < 16; ++i) {
            if (dc == 0) g_W4r[(g*NH + hht*16 + i)*KC + 512 + cm] = acc[i];
            else         g_W4p[(g*NH + hht*16 + i)*768 + cm] = acc[i];
        }
    }
    if (tid < 16) {   // bias partial
        float s = 0.f;
        for (int d = 0; d < 128; ++d) s += A2[tid*128 + d] * b_fc[d0 + d];
        if (dc == 0) g_b4a[g*NH + hht*16 + tid] = bg[hht*16 + tid] + s;
        else         g_b4b[g*NH + hht*16 + tid] = s;
    }
}

// ---------------- prep4: combine partials, blocked layouts, bias ----------------
__global__ void prep4()
{
    int idx = blockIdx.x * blockDim.x + threadIdx.x;
    if (idx < 4*320*256) {
        int hh = idx & 255;
        int gk = idx >> 8;
        int g = gk / 320, k4 = gk % 320;
        float4 v = *(const float4*)&g_W4r[(g*NH + hh)*KC + k4*4];
        if (k4 >= 128) {
            float4 p = *(const float4*)&g_W4p[(g*NH + hh)*768 + (k4 - 128)*4];
            v.x += p.x; v.y += p.y; v.z += p.z; v.w += p.w;
        }
        *(float4*)&g_W4q[idx*4] = v;
        return;
    }
    int j = idx - 4*320*256;
    if (j < 128*512) {
        int cm = j & 511, k4 = j >> 9;
        *(float4*)&g_Wscq[j*4] = *(const float4*)&g_Wscr[cm*KA + k4*4];
        return;
    }
    int m = j - 128*512;
    if (m < 4*NH) g_b4[m] = g_b4a[m] + g_b4b[m];
}

// ---------------- tiny barrier-reset (keeps launch count; idempotent) ----------------
__global__ void prep5()
{
    int tid = threadIdx.x;
    if (tid < NGRP*64) { g_garrive[tid] = 0u; g_grelease[tid] = 0u; }
}

// ---------------- per-group barrier ----------------
__device__ __forceinline__ void group_sync(int grp, unsigned int& gen)
{
    __syncthreads();
    if (threadIdx.x == 0) {
        unsigned int target = gen + 1u;
        unsigned int a = atom_add_acqrel(&g_garrive[grp*64], 1u) + 1u;
        if (a == target * 16u) {
            st_release(&g_grelease[grp*64], target);
        } else {
            while (ld_acquire(&g_grelease[grp*64]) < target) { }
        }
    }
    gen += 1u;
    __syncthreads();
}

// ---------------- persistent recurrence (k-pair packed f32x2, b-major acts) ----------------
__global__ void __launch_bounds__(NTHR, 1)
rnn_kernel(const float* __restrict__ global_w)
{
    extern __shared__ float sm[];
    const int cta = blockIdx.x, tid = threadIdx.x;
    const int lane = tid & 31, wid = tid >> 5;
    const int grp = cta >> 4, local = cta & 15;
    const int bhalf = local >> 3, ccl = local & 7;
    const int a_b0 = grp*16 + bhalf*8;
    const int a_ml = tid & 63, a_bh = (tid >> 6) & 1, a_ks = tid >> 7;
    const int sub = local;
    const int c_b0 = grp*16;
    const int c_hl = tid & 15, c_ks = tid >> 6;
    const int hh = sub*16 + c_hl;
    unsigned int gen = 0;

    // ---- register hoists ----
    float gwreg = global_w[ccl];
    float cscreg = g_csc[ccl*64 + (tid & 63)];
    float creg = 0.f;
    float bias0 = 0.f, bias1 = 0.f, bias2 = 0.f, bias3 = 0.f;
    if (tid < 256) {
        int h2 = sub*16 + (tid & 15);
        bias0 = g_b4[0*NH + h2];
        bias1 = g_b4[1*NH + h2];
        bias2 = g_b4[2*NH + h2];
        bias3 = g_b4[3*NH + h2];
    }

    // pre-stage A acts for t=0: [bi 0..7][k 0..511] (LP then h)
    for (int idx = tid; idx < 8*128; idx += NTHR) {
        int bi = idx >> 7, k4 = idx & 127;
        int b = a_b0 + bi;
        float4 v;
        if (k4 < 64) v = *(const float4*)&g_LPb[((b*NT) << 8) + k4*4];
        else         v = __ldcg((const float4*)&g_hall[(b << 8) + (k4-64)*4]);
        *(float4*)&sm[A_ACT + bi*A_BSTR + k4*4] = v;
    }
    __syncthreads();

    for (int t = 0; t < NT; ++t) {
        // ===== Phase A: scores + softmax -> s'(t) in g_sw [b][cm] =====
        {
            u64 acc2[4] = {0ull, 0ull, 0ull, 0ull};
            {
                const double2* wp = (const double2*)g_Wscq + (a_ks*32)*NCM + (ccl*64 + a_ml);
                const float*  ak = sm + A_ACT + (a_bh*4)*A_BSTR + a_ks*128;
                #define AHALF(IT, WV) { \
                    u64 w01_ = __double_as_longlong((WV).x); \
                    u64 w23_ = __double_as_longlong((WV).y); \
                    const float* app_ = ak + (IT)*4; \
                    _Pragma("unroll") \
                    for (int j_ = 0; j_ < 4; ++j_) { \
                        u64 a01_ = *(const u64*)(app_ + j_*A_BSTR); \
                        u64 a23_ = *(const u64*)(app_ + j_*A_BSTR + 2); \
                        ffma2(acc2[j_], w01_, a01_); \
                        ffma2(acc2[j_], w23_, a23_); } }
                double2 V0 = wp[0], V1 = wp[NCM];
                #pragma unroll 1
                for (int it = 0; it < 32; it += 2) {
                    double2 N0 = wp[(it+2)*NCM];     // prefetch (padded array)
                    AHALF(it, V0)
                    double2 N1 = wp[(it+3)*NCM];
                    AHALF(it+1, V1)
                    V0 = N0; V1 = N1;
                }
                #undef AHALF
            }
            {
                int base = A_PART + ((a_ks*64 + a_ml)*2 + a_bh)*5;
                #pragma unroll
                for (int j = 0; j < 4; ++j) sm[base + j] = pairsum(acc2[j]);
            }
            __syncthreads();
            {   // reduce over a_ks + csc bias; bl = batch (bh=bl>>2, j=bl&3)
                int bl = tid >> 6, m = tid & 63;
                float s = cscreg;
                #pragma unroll
                for (int ks = 0; ks < 4; ++ks)
                    s += sm[A_PART + ((ks*64 + m)*2 + (bl >> 2))*5 + (bl & 3)];
                sm[A_SCORE + bl*64 + m] = s;
            }
            __syncthreads();
            if (wid < 8) {   // softmax for batch wid; scale by global_w[ccl]
                float v0 = sm[A_SCORE + wid*64 + lane];
                float v1 = sm[A_SCORE + wid*64 + 32 + lane];
                float mx = fmaxf(v0, v1);
                #pragma unroll
                for (int o = 16; o; o >>= 1) mx = fmaxf(mx, __shfl_xor_sync(0xffffffffu, mx, o));
                float e0 = expf(v0 - mx), e1 = expf(v1 - mx);
                float s = e0 + e1;
                #pragma unroll
                for (int o = 16; o; o >>= 1) s += __shfl_xor_sync(0xffffffffu, s, o);
                float sc = gwreg / s;
                int b = a_b0 + wid;
                __stcg(&g_sw[b*NCM + ccl*64 + lane],      e0*sc);
                __stcg(&g_sw[b*NCM + ccl*64 + 32 + lane], e1*sc);
            }
        }

        // stage C z/zp(t) (h-independent) BEFORE the barrier: [bi][k<512]
        for (int idx = tid; idx < 16*128; idx += NTHR) {
            int bi = idx >> 7, k4 = idx & 127;
            int b = c_b0 + bi, k = k4*4;
            float4 v;
            if (k < 256) v = *(const float4*)&g_Zb [((b*NT + t) << 8) + k];
            else         v = *(const float4*)&g_ZPb[((b*NT + t) << 8) + (k - 256)];
            *(float4*)&sm[bi*C_BSTR + k] = v;
        }
        group_sync(grp, gen);

        // stage C s'(t) + h(t): [bi][k 512..1280)
        for (int idx = tid; idx < 16*192; idx += NTHR) {
            int bi = idx / 192, kr4 = idx % 192;
            int b = c_b0 + bi, k = 512 + kr4*4;
            float4 v;
            if (k < 1024) v = __ldcg((const float4*)&g_sw[(b << 9) + (k - 512)]);
            else          v = __ldcg((const float4*)&g_hall[((t*NB + b) << 8) + (k - 1024)]);
            *(float4*)&sm[bi*C_BSTR + k] = v;
        }
        __syncthreads();

        // ===== Phase C: 4-gate GEMM, K=1280, k-pair packed f32x2 =====
        {
            u64 acc2[16];
            #pragma unroll
            for (int i = 0; i < 16; ++i) acc2[i] = 0ull;
            {
                const int c_bq = (tid >> 4) & 3;
                const int k40 = c_ks * 40;
                const double2* w0 = (const double2*)g_W4q + ((0*320 + k40)*NH + hh);
                const double2* w1 = (const double2*)g_W4q + ((1*320 + k40)*NH + hh);
                const double2* w2 = (const double2*)g_W4q + ((2*320 + k40)*NH + hh);
                const double2* w3 = (const double2*)g_W4q + ((3*320 + k40)*NH + hh);
                const float*  ak = sm + (c_bq*4)*C_BSTR + c_ks*160;
                #define CHALF(IT, WA, WB, WC, WD) { \
                    u64 wa01_ = __double_as_longlong((WA).x), wa23_ = __double_as_longlong((WA).y); \
                    u64 wb01_ = __double_as_longlong((WB).x), wb23_ = __double_as_longlong((WB).y); \
                    u64 wc01_ = __double_as_longlong((WC).x), wc23_ = __double_as_longlong((WC).y); \
                    u64 wd01_ = __double_as_longlong((WD).x), wd23_ = __double_as_longlong((WD).y); \
                    const float* app_ = ak + (IT)*4; \
                    _Pragma("unroll") \
                    for (int j_ = 0; j_ < 4; ++j_) { \
                        u64 a01_ = *(const u64*)(app_ + j_*C_BSTR); \
                        u64 a23_ = *(const u64*)(app_ + j_*C_BSTR + 2); \
                        ffma2(acc2[0*4+j_], wa01_, a01_); ffma2(acc2[0*4+j_], wa23_, a23_); \
                        ffma2(acc2[1*4+j_], wb01_, a01_); ffma2(acc2[1*4+j_], wb23_, a23_); \
                        ffma2(acc2[2*4+j_], wc01_, a01_); ffma2(acc2[2*4+j_], wc23_, a23_); \
                        ffma2(acc2[3*4+j_], wd01_, a01_); ffma2(acc2[3*4+j_], wd23_, a23_); } }
                double2 Wa0 = w0[0],  Wb0 = w1[0],  Wc0 = w2[0],  Wd0 = w3[0];
                double2 Wa1 = w0[NH], Wb1 = w1[NH], Wc1 = w2[NH], Wd1 = w3[NH];
                #pragma unroll 1
                for (int it = 0; it < 40; it += 2) {
                    double2 Na = w0[(it+2)*NH], Nb = w1[(it+2)*NH],
                            Nc = w2[(it+2)*NH], Nd = w3[(it+2)*NH];   // prefetch (padded)
                    CHALF(it, Wa0, Wb0, Wc0, Wd0)
                    double2 Ma = w0[(it+3)*NH], Mb = w1[(it+3)*NH],
                            Mc = w2[(it+3)*NH], Md = w3[(it+3)*NH];
                    CHALF(it+1, Wa1, Wb1, Wc1, Wd1)
                    Wa0 = Na; Wb0 = Nb; Wc0 = Nc; Wd0 = Nd;
                    Wa1 = Ma; Wb1 = Mb; Wc1 = Mc; Wd1 = Md;
                }
                #undef CHALF
            }
            __syncthreads();
            {
                const int c_bq = (tid >> 4) & 3;
                int base = (c_ks*64 + c_bq*16 + c_hl)*17;   // pad-17: conflict-free
                #pragma unroll
                for (int v = 0; v < 16; ++v) sm[base + v] = pairsum(acc2[v]);
            }
            __syncthreads();
            if (tid < 256) {   // (hl2:16, bi:16): reduce, gates, register state
                int hl2 = tid & 15, bi = tid >> 4;
                int bq = bi >> 2, j = bi & 3;
                int b = c_b0 + bi, h2 = sub*16 + hl2;
                float g0 = bias0, g1 = bias1, g2 = bias2, g3 = bias3;
                #pragma unroll
                for (int ks = 0; ks < 8; ++ks) {
                    const float* p = &sm[(ks*64 + bq*16 + hl2)*17 + j];
                    g0 += p[0]; g1 += p[4]; g2 += p[8]; g3 += p[12];
                }
                float ig = 1.f / (1.f + expf(-g0));
                float fg = 1.f / (1.f + expf(-g1));
                float og = 1.f / (1.f + expf(-g2));
                float cg = tanhf(g3);
                creg = fg * creg + ig * cg;
                float hn = og * tanhf(creg);
                __stcg(&g_hall[(((t+1)*NB + b) << 8) + h2], hn);
            }
        }

        // stage A LP(t+1) BEFORE the barrier: [bi][k<256]
        if (t + 1 < NT) {
            for (int idx = tid; idx < 8*64; idx += NTHR) {
                int bi = idx >> 6, k4 = idx & 63;
                int b = a_b0 + bi;
                *(float4*)&sm[A_ACT + bi*A_BSTR + k4*4] =
                    *(const float4*)&g_LPb[((b*NT + t + 1) << 8) + k4*4];
            }
        }
        group_sync(grp, gen);

        if (t + 1 < NT) {   // stage A h(t+1): [bi][256..512)
            for (int idx = tid; idx < 8*64; idx += NTHR) {
                int bi = idx >> 6, k4 = idx & 63;
                int b = a_b0 + bi;
                *(float4*)&sm[A_ACT + bi*A_BSTR + 256 + k4*4] =
                    __ldcg((const float4*)&g_hall[(((t+1)*NB + b) << 8) + k4*4]);
            }
            __syncthreads();
        }
    }
}

// ---------------- final: out[b,t,:] = h_{t+1} @ W_fc^T + b_fc ----------------
__global__ void out_gemm(const float* __restrict__ W_fc, const float* __restrict__ b_fc,
                         float* __restrict__ out)
{
    __shared__ float sa[16*256];
    int rt = blockIdx.x >> 2, dt = blockIdx.x & 3;
    int tid = threadIdx.x;           // 256
    int r0 = rt * 16;
    for (int idx = tid; idx < 16*64; idx += 256) {
        int row = idx >> 6, k4 = idx & 63;
        int r = r0 + row, b = r / NT, t = r % NT;
        *(float4*)&sa[row*256 + k4*4] =
            *(const float4*)&g_hall[(((t+1)*NB + b) << 8) + k4*4];
    }
    __syncthreads();
    int dl = tid & 63, rl = tid >> 6;
    int d = dt*64 + dl;
    float acc[4];
    #pragma unroll
    for (int i = 0; i < 4; ++i) acc[i] = 0.f;
    const float* wrow = W_fc + d*NH;
    #pragma unroll 4
    for (int k4 = 0; k4 < 64; ++k4) {
        float4 wv = *(const float4*)(wrow + k4*4);
        #pragma unroll
        for (int i = 0; i < 4; ++i) {
            float4 av = *(const float4*)&sa[(rl*4 + i)*256 + k4*4];
            FMA4(acc[i], wv, av);
        }
    }
    float bb = b_fc[d];
    #pragma unroll
    for (int i = 0; i < 4; ++i)
        out[(r0 + rl*4 + i)*ND + d] = acc[i] + bb;
}

// ---------------- launch ----------------
extern "C" void kernel_launch(void* const* d_in, const int* in_sizes, int n_in,
                              void* d_out, int out_size)
{
    const float* x        = (const float*)d_in[0];
    const float* xmean    = (const float*)d_in[1];
    const int*   clus     = (const int*)  d_in[2];
    const float* W_i      = (const float*)d_in[3];
    const float* b_i      = (const float*)d_in[4];
    const float* W_f      = (const float*)d_in[5];
    const float* b_f      = (const float*)d_in[6];
    const float* W_o      = (const float*)d_in[7];
    const float* b_o      = (const float*)d_in[8];
    const float* W_c      = (const float*)d_in[9];
    const float* b_c      = (const float*)d_in[10];
    const float* W_fc     = (const float*)d_in[11];
    const float* b_fc     = (const float*)d_in[12];
    const float* gz_w     = (const float*)d_in[13];
    const float* gz_b     = (const float*)d_in[14];
    const float* gzp_w    = (const float*)d_in[15];
    const float* gzp_b    = (const float*)d_in[16];
    const float* memory   = (const float*)d_in[17];
    const float* local_w  = (const float*)d_in[18];
    const float* global_w = (const float*)d_in[19];
    float* out = (float*)d_out;

    cudaFuncSetAttribute(rnn_kernel, cudaFuncAttributeMaxDynamicSharedMemorySize, SMEM_BYTES);

    prep1<<<512, 256>>>(x, xmean, clus, gz_w, gz_b, gzp_w, gzp_b, memory, local_w);
    prep2<<<32, 512>>>(W_fc, b_fc, local_w);
    prep3<<<128, 512>>>(W_i, W_f, W_o, W_c, b_i, b_f, b_o, b_c, W_fc, b_fc);
    prep4<<<1540, 256>>>();
    prep5<<<1, 512>>>();
    rnn_kernel<<<GRID, NTHR, SMEM_BYTES>>>(global_w);
    out_gemm<<<3072, 256>>>(W_fc, b_fc, out);
}

// round 13
// speedup vs baseline: 1.1024x; 1.1008x over previous
#include <cuda_runtime.h>

#define NB 128
#define NT 96
#define ND 256
#define NH 256
#define NCM 512
#define GRID 128
#define NTHR 512
#define NGRP 8

typedef unsigned long long u64;

// smem (floats): C acts [bi][k<768] b-major; partials reuse; A acts [bi][k<256]
#define C_BSTR  776
#define A_BSTR  264
#define A_ACT   (16 * C_BSTR)            // 12416
#define A_PART  (A_ACT + 8 * A_BSTR)     // 14528
#define A_SCORE (A_PART + 2560)          // 17088
#define SMEM_FLOATS (A_SCORE + 512)      // 17600
#define SMEM_BYTES  (SMEM_FLOATS * 4)    // 70400 B

__device__ float g_Zb [NB*NT*ND];        // [b][t][d]
__device__ float g_ZPb[NB*NT*ND];
__device__ float g_LPb[NB*NT*ND];
__device__ float g_hall[(NT+1)*NB*NH];   // [t][b][h]
__device__ float g_sw  [NB*NCM];         // [b][cm]
__device__ float g_mm  [NCM*ND];
__device__ float g_memT[ND*NCM];
__device__ float g_W4r [4*NH*1280];      // row-major folded gate weights (dc0)
__device__ float g_W4p [4*NH*768];       // dc1 partials, orig cols [512:1280)
__device__ float g_W4q [4*192*NH*4 + 4096];   // in-loop blocked [g][k4'][hh][4]
__device__ float g_b4a [4*NH];
__device__ float g_b4b [4*NH];
__device__ float g_b4  [4*NH];
__device__ float g_Wscr[NCM*512];
__device__ float g_Wscq[64*NCM*4 + 6144];     // in-loop blocked [k4][cm][4]
__device__ float g_csc [NCM];
__device__ float g_G0[(size_t)NB*NT*1024];    // [b][t][g*256+hh], bias folded
__device__ float g_A0[(size_t)NB*NT*512];     // [b][t][cm], csc folded
__device__ unsigned int g_garrive [NGRP*64];
__device__ unsigned int g_grelease[NGRP*64];

#define FMA4(ACC, WV, AV) ACC = fmaf((WV).x,(AV).x, fmaf((WV).y,(AV).y, fmaf((WV).z,(AV).z, fmaf((WV).w,(AV).w,(ACC)))))

__device__ __forceinline__ void ffma2(u64& acc, u64 a, u64 b) {
    asm("fma.rn.f32x2 %0, %1, %2, %0;" : "+l"(acc) : "l"(a), "l"(b));
}
__device__ __forceinline__ u64 dup2(float v) {
    u64 r; asm("mov.b64 %0, {%1, %1};" : "=l"(r) : "f"(v)); return r;
}
__device__ __forceinline__ void unpack2(u64 v, float& lo, float& hi) {
    asm("mov.b64 {%0, %1}, %2;" : "=f"(lo), "=f"(hi) : "l"(v));
}
__device__ __forceinline__ float pairsum(u64 v) {
    float lo, hi; unpack2(v, lo, hi); return lo + hi;
}
__device__ __forceinline__ unsigned atom_add_acqrel(unsigned* p, unsigned v) {
    unsigned r;
    asm volatile("atom.acq_rel.gpu.add.u32 %0, [%1], %2;" : "=r"(r) : "l"(p), "r"(v) : "memory");
    return r;
}
__device__ __forceinline__ unsigned ld_acquire(unsigned* p) {
    unsigned r;
    asm volatile("ld.acquire.gpu.u32 %0, [%1];" : "=r"(r) : "l"(p) : "memory");
    return r;
}
__device__ __forceinline__ void st_release(unsigned* p, unsigned v) {
    asm volatile("st.release.gpu.u32 [%0], %1;" :: "l"(p), "r"(v) : "memory");
}

// ---------------- prep1 ----------------
__global__ void prep1(const float* __restrict__ x, const float* __restrict__ xmean,
                      const int* __restrict__ cl32,
                      const float* __restrict__ gz_w,  const float* __restrict__ gz_b,
                      const float* __restrict__ gzp_w, const float* __restrict__ gzp_b,
                      const float* __restrict__ memory, const float* __restrict__ local_w)
{
    int tid  = blockIdx.x * blockDim.x + threadIdx.x;
    int nthr = gridDim.x * blockDim.x;
    bool is64 = (cl32[1] == 0);   // cluster vals 1..8 -> int64 high word of elem0 is 0

    for (int i = tid; i < NB*NT*ND; i += nthr) {
        int d = i & (ND - 1);
        int t = (i / ND) % NT;
        int b = i / (ND * NT);
        long long o = (((long long)b * 6) * NT + t) * ND + d;
        float xt  = x[o];
        float xl  = x[o + 1ll*NT*ND];
        float mk  = x[o + 2ll*NT*ND];
        float dt  = x[o + 3ll*NT*ND];
        float xlb = x[o + 4ll*NT*ND];
        float dtb = x[o + 5ll*NT*ND];
        float mean = xmean[t*ND + d];
        float dz  = expf(-fmaxf(dt  * gz_w[d]  + gz_b[d],  0.f));
        float dzp = expf(-fmaxf(dtb * gzp_w[d] + gzp_b[d], 0.f));
        float z  = mk*xt + (1.f - mk)*(dz *xl  + (1.f - dz )*mean);
        float zp = mk*xt + (1.f - mk)*(dzp*xlb + (1.f - dzp)*mean);
        g_Zb[i]  = z;
        g_ZPb[i] = zp;
        g_LPb[i] = local_w[d]*z + local_w[ND + d]*zp;
    }
    for (int i = tid; i < NCM*ND; i += nthr) {
        int d  = i & (ND - 1);
        int c  = i / (64 * ND);
        int cv = is64 ? cl32[2*d] : cl32[d];
        g_mm[i] = (cv == c + 1) ? memory[i] : 0.f;
    }
    for (int i = tid; i < ND*NCM; i += nthr) {
        int d = i / NCM, cm = i % NCM;
        g_memT[i] = memory[cm*ND + d];
    }
    for (int i = tid; i < NB*NH; i += nthr) g_hall[i] = 0.f;
    if (tid < NGRP*64) { g_garrive[tid] = 0u; g_grelease[tid] = 0u; }
}

// ---------------- prep2: folded score weights + csc ----------------
__global__ void prep2(const float* __restrict__ W_fc, const float* __restrict__ b_fc,
                      const float* __restrict__ local_w)
{
    __shared__ float A[16*256];
    int cmt = blockIdx.x;            // 0..31
    int tid = threadIdx.x;           // 512
    for (int idx = tid; idx < 16*256; idx += 512) {
        int ci = idx >> 8, d = idx & 255;
        float mmv = g_mm[(cmt*16 + ci)*ND + d];
        A[idx] = local_w[2*ND + d] * mmv;
        g_Wscr[(cmt*16 + ci)*512 + d] = mmv;
    }
    __syncthreads();
    int j = tid & 255, half = tid >> 8;
    float acc[8];
    #pragma unroll
    for (int i = 0; i < 8; ++i) acc[i] = 0.f;
    for (int d = 0; d < 256; ++d) {
        float wf = W_fc[d*ND + j];
        #pragma unroll
        for (int i = 0; i < 8; ++i) acc[i] = fmaf(A[(half*8+i)*256 + d], wf, acc[i]);
    }
    #pragma unroll
    for (int i = 0; i < 8; ++i)
        g_Wscr[(cmt*16 + half*8 + i)*512 + 256 + j] = acc[i];
    if (tid < 16) {
        float s = 0.f;
        for (int d = 0; d < 256; ++d) s += A[tid*256 + d] * b_fc[d];
        g_csc[cmt*16 + tid] = s;
    }
}

// ---------------- prep3: folded gate weights, 2-way d-split ----------------
__global__ void prep3(const float* __restrict__ W_i, const float* __restrict__ W_f,
                      const float* __restrict__ W_o, const float* __restrict__ W_c,
                      const float* __restrict__ b_i, const float* __restrict__ b_f,
                      const float* __restrict__ b_o, const float* __restrict__ b_c,
                      const float* __restrict__ W_fc, const float* __restrict__ b_fc)
{
    __shared__ float A1[16*128];
    __shared__ float A2[16*128];
    int bx = blockIdx.x;                 // 128
    int g = bx >> 5, hht = (bx >> 1) & 15, dc = bx & 1;
    int d0 = dc * 128;
    const float* Wg = (g == 0) ? W_i : (g == 1) ? W_f : (g == 2) ? W_o : W_c;
    const float* bg = (g == 0) ? b_i : (g == 1) ? b_f : (g == 2) ? b_o : b_c;
    int tid = threadIdx.x;   // 512

    for (int idx = tid; idx < 16*128; idx += 512) {
        int hi = idx >> 7, d = idx & 127;
        int row = hht*16 + hi;
        A1[idx] = Wg[row*1280 + 768 + d0 + d];
        A2[idx] = Wg[row*1280 + 512 + d0 + d];
    }
    if (dc == 0) {
        for (int idx = tid; idx < 16*512; idx += 512) {
            int hi = idx >> 9, k = idx & 511;
            int row = hht*16 + hi;
            g_W4r[(g*NH + row)*1280 + k] = Wg[row*1280 + k];
        }
    }
    __syncthreads();
    {   // h segment partial
        int j = tid & 255, half = tid >> 8;
        float acc[8];
        #pragma unroll
        for (int i = 0; i < 8; ++i) acc[i] = 0.f;
        for (int d = 0; d < 128; ++d) {
            float wf = W_fc[(d0 + d)*ND + j];
            #pragma unroll
            for (int i = 0; i < 8; ++i) acc[i] = fmaf(A2[(half*8+i)*128 + d], wf, acc[i]);
        }
        #pragma unroll
        for (int i = 0; i < 8; ++i) {
            int hhr = hht*16 + half*8 + i;
            if (dc == 0) g_W4r[(g*NH + hhr)*1280 + 1024 + j] = Wg[hhr*1280 + 1024 + j] + acc[i];
            else         g_W4p[(g*NH + hhr)*768 + 512 + j] = acc[i];
        }
    }
    {   // s' segment partial
        int cm = tid;
        float acc[16];
        #pragma unroll
        for (int i = 0; i < 16; ++i) acc[i] = 0.f;
        for (int d = 0; d < 128; ++d) {
            float mt = g_memT[(d0 + d)*NCM + cm];
            #pragma unroll
            for (int i = 0; i < 16; ++i) acc[i] = fmaf(A1[i*128 + d], mt, acc[i]);
        }
        #pragma unroll
        for (int i = 0; i < 16; ++i) {
            if (dc == 0) g_W4r[(g*NH + hht*16 + i)*1280 + 512 + cm] = acc[i];
            else         g_W4p[(g*NH + hht*16 + i)*768 + cm] = acc[i];
        }
    }
    if (tid < 16) {
        float s = 0.f;
        for (int d = 0; d < 128; ++d) s += A2[tid*128 + d] * b_fc[d0 + d];
        if (dc == 0) g_b4a[g*NH + hht*16 + tid] = bg[hht*16 + tid] + s;
        else         g_b4b[g*NH + hht*16 + tid] = s;
    }
}

// ---------------- prep4: in-loop blocked layouts (orig k>=512) + b4 ----------------
__global__ void prep4()
{
    int idx = blockIdx.x * blockDim.x + threadIdx.x;
    if (idx < 4*192*256) {
        int hh = idx & 255;
        int gk = idx >> 8;
        int g = gk / 192, k4 = gk % 192;
        float4 v = *(const float4*)&g_W4r[(g*NH + hh)*1280 + 512 + k4*4];
        float4 p = *(const float4*)&g_W4p[(g*NH + hh)*768 + k4*4];
        v.x += p.x; v.y += p.y; v.z += p.z; v.w += p.w;
        *(float4*)&g_W4q[idx*4] = v;
        return;
    }
    int j = idx - 4*192*256;
    if (j < 64*512) {
        int cm = j & 511, k4 = j >> 9;
        *(float4*)&g_Wscq[j*4] = *(const float4*)&g_Wscr[cm*512 + 256 + k4*4];
        return;
    }
    int m = j - 64*512;
    if (m < 4*NH) g_b4[m] = g_b4a[m] + g_b4b[m];
}

// ---------------- pc_gemm: G0 = [z;zp]·W^T + b4 ; A0 = LP·Wsc^T + csc ----------------
__global__ void __launch_bounds__(256, 4) pc_gemm()
{
    __shared__ float sa[64*68];
    __shared__ float sw[64*68];
    int rt = blockIdx.x;             // 0..191, rows = b*96+t
    int yy = blockIdx.y;             // 0..23
    bool isG = (yy < 16);
    int ct = isG ? yy : (yy - 16);
    const int COLS = isG ? 1024 : 512;
    const int KK   = isG ? 512 : 256;
    const int KROW = isG ? 1280 : 512;
    const float* WR   = isG ? g_W4r : g_Wscr;
    const float* BIAS = isG ? g_b4 : g_csc;
    float* OUT = isG ? g_G0 : g_A0;
    int tid = threadIdx.x;
    int tr = tid >> 4, tc = tid & 15;
    int r0 = tr*4, c0l = tc*4;
    u64 acc[4][2];
    #pragma unroll
    for (int i = 0; i < 4; ++i) { acc[i][0] = 0ull; acc[i][1] = 0ull; }

    for (int kc = 0; kc < KK; kc += 64) {
        for (int i = tid; i < 1024; i += 256) {      // acts 64r x 64k (float4)
            int r = i >> 4, k4 = i & 15;
            int R = rt*64 + r;
            int kg = kc + k4*4;
            const float* src;
            if (isG) src = (kg < 256) ? &g_Zb[(R << 8) + kg] : &g_ZPb[(R << 8) + kg - 256];
            else     src = &g_LPb[(R << 8) + kg];
            *(float4*)&sa[r*68 + k4*4] = *(const float4*)src;
        }
        for (int e = tid; e < 4096; e += 256) {      // weights 64c x 64k -> sw[k][c]
            int c = e >> 6, k = e & 63;
            sw[k*68 + c] = WR[(size_t)(ct*64 + c)*KROW + kc + k];
        }
        __syncthreads();
        #pragma unroll 4
        for (int k = 0; k < 64; ++k) {
            double2 wv = *(const double2*)&sw[k*68 + c0l];
            u64 w01 = __double_as_longlong(wv.x);
            u64 w23 = __double_as_longlong(wv.y);
            #pragma unroll
            for (int i = 0; i < 4; ++i) {
                u64 av = dup2(sa[(r0 + i)*68 + k]);
                ffma2(acc[i][0], av, w01);
                ffma2(acc[i][1], av, w23);
            }
        }
        __syncthreads();
    }
    float4 bv = *(const float4*)&BIAS[ct*64 + c0l];
    #pragma unroll
    for (int i = 0; i < 4; ++i) {
        float o0, o1, o2, o3;
        unpack2(acc[i][0], o0, o1);
        unpack2(acc[i][1], o2, o3);
        int R = rt*64 + r0 + i;
        float4 ov = make_float4(o0 + bv.x, o1 + bv.y, o2 + bv.z, o3 + bv.w);
        *(float4*)&OUT[(size_t)R*COLS + ct*64 + c0l] = ov;
    }
}

// ---------------- per-group barrier ----------------
__device__ __forceinline__ void group_sync(int grp, unsigned int& gen)
{
    __syncthreads();
    if (threadIdx.x == 0) {
        unsigned int target = gen + 1u;
        unsigned int a = atom_add_acqrel(&g_garrive[grp*64], 1u) + 1u;
        if (a == target * 16u) {
            st_release(&g_grelease[grp*64], target);
        } else {
            while (ld_acquire(&g_grelease[grp*64]) < target) { }
        }
    }
    gen += 1u;
    __syncthreads();
}

// ---------------- persistent recurrence: in-loop K = h-dependent only ----------------
__global__ void __launch_bounds__(NTHR, 1)
rnn_kernel(const float* __restrict__ global_w)
{
    extern __shared__ float sm[];
    const int cta = blockIdx.x, tid = threadIdx.x;
    const int lane = tid & 31, wid = tid >> 5;
    const int grp = cta >> 4, local = cta & 15;
    const int bhalf = local >> 3, ccl = local & 7;
    const int a_b0 = grp*16 + bhalf*8;
    const int a_ml = tid & 63, a_bh = (tid >> 6) & 1, a_ks = tid >> 7;
    const int sub = local;
    const int c_b0 = grp*16;
    const int c_hl = tid & 15, c_ks = tid >> 6;
    const int hh = sub*16 + c_hl;
    unsigned int gen = 0;

    float gwreg = global_w[ccl];
    float creg = 0.f;

    // pre-stage A acts (h(0)=0): [bi<8][k<256]
    for (int idx = tid; idx < 8*64; idx += NTHR) {
        int bi = idx >> 6, k4 = idx & 63;
        *(float4*)&sm[A_ACT + bi*A_BSTR + k4*4] =
            *(const float4*)&g_hall[((a_b0 + bi) << 8) + k4*4];
    }
    __syncthreads();

    for (int t = 0; t < NT; ++t) {
        // ---- prefetch precomputed contributions for step t ----
        float g0r0 = 0.f, g0r1 = 0.f, g0r2 = 0.f, g0r3 = 0.f;
        if (tid < 256) {
            int bi = tid >> 4, h2 = sub*16 + (tid & 15);
            const float* p = g_G0 + (size_t)((c_b0 + bi)*NT + t)*1024 + h2;
            g0r0 = __ldcg(p);       g0r1 = __ldcg(p + 256);
            g0r2 = __ldcg(p + 512); g0r3 = __ldcg(p + 768);
        }
        float a0r = __ldcg(&g_A0[(size_t)((a_b0 + (tid >> 6))*NT + t)*512 + ccl*64 + (tid & 63)]);

        // ===== Phase A: scores(h) + A0 + softmax -> s'(t) in g_sw =====
        {
            u64 acc2[4] = {0ull, 0ull, 0ull, 0ull};
            {
                const double2* wp = (const double2*)g_Wscq + (a_ks*16)*NCM + (ccl*64 + a_ml);
                const float*  ak = sm + A_ACT + (a_bh*4)*A_BSTR + a_ks*64;
                #define AHALF(IT, WV) { \
                    u64 w01_ = __double_as_longlong((WV).x); \
                    u64 w23_ = __double_as_longlong((WV).y); \
                    const float* app_ = ak + (IT)*4; \
                    _Pragma("unroll") \
                    for (int j_ = 0; j_ < 4; ++j_) { \
                        u64 a01_ = *(const u64*)(app_ + j_*A_BSTR); \
                        u64 a23_ = *(const u64*)(app_ + j_*A_BSTR + 2); \
                        ffma2(acc2[j_], w01_, a01_); \
                        ffma2(acc2[j_], w23_, a23_); } }
                double2 V0 = wp[0], V1 = wp[NCM];
                #pragma unroll 1
                for (int it = 0; it < 16; it += 2) {
                    double2 N0 = wp[(it+2)*NCM];
                    AHALF(it, V0)
                    double2 N1 = wp[(it+3)*NCM];
                    AHALF(it+1, V1)
                    V0 = N0; V1 = N1;
                }
                #undef AHALF
            }
            {
                int base = A_PART + ((a_ks*64 + a_ml)*2 + a_bh)*5;
                #pragma unroll
                for (int j = 0; j < 4; ++j) sm[base + j] = pairsum(acc2[j]);
            }
            __syncthreads();
            {
                int bl = tid >> 6, m = tid & 63;
                float s = a0r;
                #pragma unroll
                for (int ks = 0; ks < 4; ++ks)
                    s += sm[A_PART + ((ks*64 + m)*2 + (bl >> 2))*5 + (bl & 3)];
                sm[A_SCORE + bl*64 + m] = s;
            }
            __syncthreads();
            if (wid < 8) {
                float v0 = sm[A_SCORE + wid*64 + lane];
                float v1 = sm[A_SCORE + wid*64 + 32 + lane];
                float mx = fmaxf(v0, v1);
                #pragma unroll
                for (int o = 16; o; o >>= 1) mx = fmaxf(mx, __shfl_xor_sync(0xffffffffu, mx, o));
                float e0 = expf(v0 - mx), e1 = expf(v1 - mx);
                float s = e0 + e1;
                #pragma unroll
                for (int o = 16; o; o >>= 1) s += __shfl_xor_sync(0xffffffffu, s, o);
                float sc = gwreg / s;
                int b = a_b0 + wid;
                __stcg(&g_sw[b*NCM + ccl*64 + lane],      e0*sc);
                __stcg(&g_sw[b*NCM + ccl*64 + 32 + lane], e1*sc);
            }
        }
        group_sync(grp, gen);   // s'(t) complete for group

        // stage C acts: s' [0:512), h(t) [512:768)   [bi][k]
        for (int idx = tid; idx < 16*192; idx += NTHR) {
            int bi = idx / 192, k4 = idx % 192;
            int b = c_b0 + bi, k = k4*4;
            float4 v;
            if (k < 512) v = __ldcg((const float4*)&g_sw[(b << 9) + k]);
            else         v = __ldcg((const float4*)&g_hall[((t*NB + b) << 8) + (k - 512)]);
            *(float4*)&sm[bi*C_BSTR + k] = v;
        }
        __syncthreads();

        // ===== Phase C: 4-gate GEMM over K=768, k-pair packed f32x2 =====
        {
            u64 acc2[16];
            #pragma unroll
            for (int i = 0; i < 16; ++i) acc2[i] = 0ull;
            {
                const int c_bq = (tid >> 4) & 3;
                const int k24 = c_ks * 24;
                const double2* w0 = (const double2*)g_W4q + ((0*192 + k24)*NH + hh);
                const double2* w1 = (const double2*)g_W4q + ((1*192 + k24)*NH + hh);
                const double2* w2 = (const double2*)g_W4q + ((2*192 + k24)*NH + hh);
                const double2* w3 = (const double2*)g_W4q + ((3*192 + k24)*NH + hh);
                const float*  ak = sm + (c_bq*4)*C_BSTR + c_ks*96;
                #define CHALF(IT, WA, WB, WC, WD) { \
                    u64 wa01_ = __double_as_longlong((WA).x), wa23_ = __double_as_longlong((WA).y); \
                    u64 wb01_ = __double_as_longlong((WB).x), wb23_ = __double_as_longlong((WB).y); \
                    u64 wc01_ = __double_as_longlong((WC).x), wc23_ = __double_as_longlong((WC).y); \
                    u64 wd01_ = __double_as_longlong((WD).x), wd23_ = __double_as_longlong((WD).y); \
                    const float* app_ = ak + (IT)*4; \
                    _Pragma("unroll") \
                    for (int j_ = 0; j_ < 4; ++j_) { \
                        u64 a01_ = *(const u64*)(app_ + j_*C_BSTR); \
                        u64 a23_ = *(const u64*)(app_ + j_*C_BSTR + 2); \
                        ffma2(acc2[0*4+j_], wa01_, a01_); ffma2(acc2[0*4+j_], wa23_, a23_); \
                        ffma2(acc2[1*4+j_], wb01_, a01_); ffma2(acc2[1*4+j_], wb23_, a23_); \
                        ffma2(acc2[2*4+j_], wc01_, a01_); ffma2(acc2[2*4+j_], wc23_, a23_); \
                        ffma2(acc2[3*4+j_], wd01_, a01_); ffma2(acc2[3*4+j_], wd23_, a23_); } }
                double2 Wa0 = w0[0],  Wb0 = w1[0],  Wc0 = w2[0],  Wd0 = w3[0];
                double2 Wa1 = w0[NH], Wb1 = w1[NH], Wc1 = w2[NH], Wd1 = w3[NH];
                #pragma unroll 1
                for (int it = 0; it < 24; it += 2) {
                    double2 Na = w0[(it+2)*NH], Nb = w1[(it+2)*NH],
                            Nc = w2[(it+2)*NH], Nd = w3[(it+2)*NH];
                    CHALF(it, Wa0, Wb0, Wc0, Wd0)
                    double2 Ma = w0[(it+3)*NH], Mb = w1[(it+3)*NH],
                            Mc = w2[(it+3)*NH], Md = w3[(it+3)*NH];
                    CHALF(it+1, Wa1, Wb1, Wc1, Wd1)
                    Wa0 = Na; Wb0 = Nb; Wc0 = Nc; Wd0 = Nd;
                    Wa1 = Ma; Wb1 = Mb; Wc1 = Mc; Wd1 = Md;
                }
                #undef CHALF
            }
            __syncthreads();
            {
                const int c_bq = (tid >> 4) & 3;
                int base = (c_ks*64 + c_bq*16 + c_hl)*17;
                #pragma unroll
                for (int v = 0; v < 16; ++v) sm[base + v] = pairsum(acc2[v]);
            }
            __syncthreads();
            if (tid < 256) {   // reduce 8 ks + G0, gates, register state
                int hl2 = tid & 15, bi = tid >> 4;
                int bq = bi >> 2, j = bi & 3;
                int b = c_b0 + bi, h2 = sub*16 + hl2;
                float g0 = g0r0, g1 = g0r1, g2 = g0r2, g3 = g0r3;
                #pragma unroll
                for (int ks = 0; ks < 8; ++ks) {
                    const float* p = &sm[(ks*64 + bq*16 + hl2)*17 + j];
                    g0 += p[0]; g1 += p[4]; g2 += p[8]; g3 += p[12];
                }
                float ig = 1.f / (1.f + expf(-g0));
                float fg = 1.f / (1.f + expf(-g1));
                float og = 1.f / (1.f + expf(-g2));
                float cg = tanhf(g3);
                creg = fg * creg + ig * cg;
                float hn = og * tanhf(creg);
                __stcg(&g_hall[(((t+1)*NB + b) << 8) + h2], hn);
            }
        }
        group_sync(grp, gen);   // h(t+1) complete for group

        if (t + 1 < NT) {   // stage A h(t+1): [bi<8][k<256]
            for (int idx = tid; idx < 8*64; idx += NTHR) {
                int bi = idx >> 6, k4 = idx & 63;
                *(float4*)&sm[A_ACT + bi*A_BSTR + k4*4] =
                    __ldcg((const float4*)&g_hall[(((t+1)*NB + a_b0 + bi) << 8) + k4*4]);
            }
            __syncthreads();
        }
    }
}

// ---------------- final: out[b,t,:] = h_{t+1} @ W_fc^T + b_fc ----------------
__global__ void out_gemm(const float* __restrict__ W_fc, const float* __restrict__ b_fc,
                         float* __restrict__ out)
{
    __shared__ float sa[16*256];
    int rt = blockIdx.x >> 2, dt = blockIdx.x & 3;
    int tid = threadIdx.x;           // 256
    int r0 = rt * 16;
    for (int idx = tid; idx < 16*64; idx += 256) {
        int row = idx >> 6, k4 = idx & 63;
        int r = r0 + row, b = r / NT, t = r % NT;
        *(float4*)&sa[row*256 + k4*4] =
            *(const float4*)&g_hall[(((t+1)*NB + b) << 8) + k4*4];
    }
    __syncthreads();
    int dl = tid & 63, rl = tid >> 6;
    int d = dt*64 + dl;
    float acc[4];
    #pragma unroll
    for (int i = 0; i < 4; ++i) acc[i] = 0.f;
    const float* wrow = W_fc + d*NH;
    #pragma unroll 4
    for (int k4 = 0; k4 < 64; ++k4) {
        float4 wv = *(const float4*)(wrow + k4*4);
        #pragma unroll
        for (int i = 0; i < 4; ++i) {
            float4 av = *(const float4*)&sa[(rl*4 + i)*256 + k4*4];
            FMA4(acc[i], wv, av);
        }
    }
    float bb = b_fc[d];
    #pragma unroll
    for (int i = 0; i < 4; ++i)
        out[(r0 + rl*4 + i)*ND + d] = acc[i] + bb;
}

// ---------------- launch ----------------
extern "C" void kernel_launch(void* const* d_in, const int* in_sizes, int n_in,
                              void* d_out, int out_size)
{
    const float* x        = (const float*)d_in[0];
    const float* xmean    = (const float*)d_in[1];
    const int*   clus     = (const int*)  d_in[2];
    const float* W_i      = (const float*)d_in[3];
    const float* b_i      = (const float*)d_in[4];
    const float* W_f      = (const float*)d_in[5];
    const float* b_f      = (const float*)d_in[6];
    const float* W_o      = (const float*)d_in[7];
    const float* b_o      = (const float*)d_in[8];
    const float* W_c      = (const float*)d_in[9];
    const float* b_c      = (const float*)d_in[10];
    const float* W_fc     = (const float*)d_in[11];
    const float* b_fc     = (const float*)d_in[12];
    const float* gz_w     = (const float*)d_in[13];
    const float* gz_b     = (const float*)d_in[14];
    const float* gzp_w    = (const float*)d_in[15];
    const float* gzp_b    = (const float*)d_in[16];
    const float* memory   = (const float*)d_in[17];
    const float* local_w  = (const float*)d_in[18];
    const float* global_w = (const float*)d_in[19];
    float* out = (float*)d_out;

    cudaFuncSetAttribute(rnn_kernel, cudaFuncAttributeMaxDynamicSharedMemorySize, SMEM_BYTES);

    prep1<<<512, 256>>>(x, xmean, clus, gz_w, gz_b, gzp_w, gzp_b, memory, local_w);
    prep2<<<32, 512>>>(W_fc, b_fc, local_w);
    prep3<<<128, 512>>>(W_i, W_f, W_o, W_c, b_i, b_f, b_o, b_c, W_fc, b_fc);
    prep4<<<900, 256>>>();
    pc_gemm<<<dim3(192, 24), 256>>>();
    rnn_kernel<<<GRID, NTHR, SMEM_BYTES>>>(global_w);
    out_gemm<<<3072, 256>>>(W_fc, b_fc, out);
}